// round 1
// baseline (speedup 1.0000x reference)
#include <cuda_runtime.h>
#include <float.h>

#define BATCH 2
#define NSEQ  2048
#define DIM   512
#define H     8
#define DH    64
#define INNER 512
#define M_TOT (BATCH*NSEQ)   /* 4096 */
#define QKV_N (3*INNER)      /* 1536 */
#define WINDOW 256
#define MAXRANGE 1024

// Scratch (device globals; allocation-free per harness rules)
__device__ float g_q[BATCH*H*NSEQ*DH];    // [b,h,n,d]
__device__ float g_k[BATCH*H*NSEQ*DH];
__device__ float g_v[BATCH*H*NSEQ*DH];
__device__ float g_ao[BATCH*NSEQ*INNER];  // [b,n,h*d]

// ---------------------------------------------------------------------------
// Kernel 1: qkv = x @ w_qkv, scattered into q/k/v [b,h,n,d] layouts.
// Block tile 128x64, 256 threads, 8x4 per thread, BK=16.
// ---------------------------------------------------------------------------
__global__ void qkv_gemm_kernel(const float* __restrict__ A,
                                const float* __restrict__ Bw)
{
    __shared__ float As[128][17];   // padded to kill bank conflicts on col reads
    __shared__ float Bs[16][64];

    const int n0 = blockIdx.x * 64;
    const int m0 = blockIdx.y * 128;
    const int tid = threadIdx.x;
    const int tx = tid & 15, ty = tid >> 4;

    float c[8][4] = {};

    for (int k0 = 0; k0 < DIM; k0 += 16) {
        #pragma unroll
        for (int p = 0; p < 2; p++) {
            int id = tid + p * 256;          // 512 float4 loads for 128x16 tile
            int r  = id >> 2;
            int c4 = (id & 3) * 4;
            float4 a4 = *(const float4*)&A[(size_t)(m0 + r) * DIM + k0 + c4];
            As[r][c4+0] = a4.x; As[r][c4+1] = a4.y;
            As[r][c4+2] = a4.z; As[r][c4+3] = a4.w;
        }
        {
            int r  = tid >> 4;
            int c4 = (tid & 15) * 4;
            *(float4*)&Bs[r][c4] =
                *(const float4*)&Bw[(size_t)(k0 + r) * QKV_N + n0 + c4];
        }
        __syncthreads();

        #pragma unroll
        for (int kk = 0; kk < 16; kk++) {
            float4 b4 = *(float4*)&Bs[kk][tx * 4];
            #pragma unroll
            for (int i = 0; i < 8; i++) {
                float a = As[ty * 8 + i][kk];
                c[i][0] += a * b4.x; c[i][1] += a * b4.y;
                c[i][2] += a * b4.z; c[i][3] += a * b4.w;
            }
        }
        __syncthreads();
    }

    // Scatter epilogue. Column block is 64-aligned so t and h are constant.
    const int t = n0 >> 9;            // 0=q, 1=k, 2=v
    const int h = (n0 >> 6) & 7;
    float* dst = (t == 0) ? g_q : (t == 1) ? g_k : g_v;

    #pragma unroll
    for (int i = 0; i < 8; i++) {
        int m  = m0 + ty * 8 + i;
        int bb = m >> 11;             // / NSEQ
        int n  = m & (NSEQ - 1);
        float* row = dst + ((size_t)(bb * H + h) * NSEQ + n) * DH + tx * 4;
        row[0] = c[i][0]; row[1] = c[i][1]; row[2] = c[i][2]; row[3] = c[i][3];
    }
}

// ---------------------------------------------------------------------------
// Kernel 2: streaming (flash-style) attention with annulus mask + tile skip.
// Grid: (32 q-tiles, 16 b*h). 256 threads, 16x16 grid, 4x4 micro-tiles.
// Dynamic smem: Qs[64][66] + Kt[64][65] + Vs[64][64] + Ps[64][66]
// ---------------------------------------------------------------------------
#define QS(r,c_) Qs[(r)*66 + (c_)]
#define KT(d_,k_) Kt[(d_)*65 + (k_)]
#define VS(r,c_) Vs[(r)*64 + (c_)]
#define PS(r,c_) Ps[(r)*66 + (c_)]

__global__ void attn_kernel()
{
    extern __shared__ float sm[];
    float* Qs = sm;                       // 64*66
    float* Kt = Qs + 64 * 66;             // 64*65  (Kt[dcol][key])
    float* Vs = Kt + 64 * 65;             // 64*64
    float* Ps = Vs + 64 * 64;             // 64*66

    const int bh = blockIdx.y;            // 0..15
    const int qt = blockIdx.x;            // 0..31
    const int qbase = qt * 64;
    const float* Q = g_q + (size_t)bh * NSEQ * DH;
    const float* K = g_k + (size_t)bh * NSEQ * DH;
    const float* V = g_v + (size_t)bh * NSEQ * DH;

    const int tid = threadIdx.x;
    const int tx = tid & 15, ty = tid >> 4;
    const float scale = 0.125f;           // 1/sqrt(64)

    // Load Q tile (64x64): 1024 float4, 4 per thread
    #pragma unroll
    for (int p = 0; p < 4; p++) {
        int id = tid + p * 256;
        int r  = id >> 4;
        int c4 = (id & 15) * 4;
        float4 q4 = *(const float4*)&Q[(size_t)(qbase + r) * DH + c4];
        QS(r, c4+0) = q4.x; QS(r, c4+1) = q4.y;
        QS(r, c4+2) = q4.z; QS(r, c4+3) = q4.w;
    }

    float m_i[4], l_i[4], acc[4][4];
    #pragma unroll
    for (int i = 0; i < 4; i++) {
        m_i[i] = -FLT_MAX; l_i[i] = 0.f;
        #pragma unroll
        for (int j = 0; j < 4; j++) acc[i][j] = 0.f;
    }

    for (int kt = 0; kt < NSEQ / 64; kt++) {
        const int kb = kt * 64;
        // tile-level annulus skip: fully masked iff dmin>WINDOW && dmax<=MAXRANGE
        int diff = qbase - kb;
        int ad = diff < 0 ? -diff : diff;
        int dmin = ad > 63 ? ad - 63 : 0;
        int dmax = ad + 63;
        if (dmin > WINDOW && dmax <= MAXRANGE) continue;   // uniform per block

        __syncthreads();  // previous PV reads of Kt/Vs/Ps done (and Q visible)

        // Load K (transposed into Kt[d][key]) and V (natural) tiles
        #pragma unroll
        for (int p = 0; p < 4; p++) {
            int id = tid + p * 256;
            int r  = id >> 4;
            int c4 = (id & 15) * 4;
            float4 k4 = *(const float4*)&K[(size_t)(kb + r) * DH + c4];
            KT(c4+0, r) = k4.x; KT(c4+1, r) = k4.y;
            KT(c4+2, r) = k4.z; KT(c4+3, r) = k4.w;
            *(float4*)&VS(r, c4) = *(const float4*)&V[(size_t)(kb + r) * DH + c4];
        }
        __syncthreads();

        // S = Q K^T  (4x4 per thread)
        float s[4][4] = {};
        #pragma unroll 4
        for (int k = 0; k < 64; k++) {
            float a0 = QS(ty*4+0, k), a1 = QS(ty*4+1, k);
            float a2 = QS(ty*4+2, k), a3 = QS(ty*4+3, k);
            float b0 = KT(k, tx*4+0), b1 = KT(k, tx*4+1);
            float b2 = KT(k, tx*4+2), b3 = KT(k, tx*4+3);
            s[0][0]+=a0*b0; s[0][1]+=a0*b1; s[0][2]+=a0*b2; s[0][3]+=a0*b3;
            s[1][0]+=a1*b0; s[1][1]+=a1*b1; s[1][2]+=a1*b2; s[1][3]+=a1*b3;
            s[2][0]+=a2*b0; s[2][1]+=a2*b1; s[2][2]+=a2*b2; s[2][3]+=a2*b3;
            s[3][0]+=a3*b0; s[3][1]+=a3*b1; s[3][2]+=a3*b2; s[3][3]+=a3*b3;
        }

        // scale + mask
        #pragma unroll
        for (int i = 0; i < 4; i++) {
            int qi = qbase + ty * 4 + i;
            #pragma unroll
            for (int j = 0; j < 4; j++) {
                int kj = kb + tx * 4 + j;
                int d = qi - kj; int adx = d < 0 ? -d : d;
                float sv = s[i][j] * scale;
                if (adx > WINDOW && adx <= MAXRANGE) sv = -FLT_MAX;
                s[i][j] = sv;
            }
        }

        // online softmax per row (row group = 16 lanes, same half-warp)
        #pragma unroll
        for (int i = 0; i < 4; i++) {
            float rm = fmaxf(fmaxf(s[i][0], s[i][1]), fmaxf(s[i][2], s[i][3]));
            #pragma unroll
            for (int off = 8; off >= 1; off >>= 1)
                rm = fmaxf(rm, __shfl_xor_sync(0xffffffffu, rm, off));
            float mnew = fmaxf(m_i[i], rm);
            float corr = __expf(m_i[i] - mnew);
            m_i[i] = mnew;
            float rs = 0.f;
            #pragma unroll
            for (int j = 0; j < 4; j++) {
                float p = __expf(s[i][j] - mnew);
                s[i][j] = p;
                rs += p;
            }
            #pragma unroll
            for (int off = 8; off >= 1; off >>= 1)
                rs += __shfl_xor_sync(0xffffffffu, rs, off);
            l_i[i] = l_i[i] * corr + rs;
            #pragma unroll
            for (int j = 0; j < 4; j++) acc[i][j] *= corr;
            // write P tile
            #pragma unroll
            for (int j = 0; j < 4; j++) PS(ty*4+i, tx*4+j) = s[i][j];
        }
        __syncthreads();

        // O += P @ V  (4x4 per thread over the 64 keys of this tile)
        #pragma unroll 4
        for (int k = 0; k < 64; k++) {
            float p0 = PS(ty*4+0, k), p1 = PS(ty*4+1, k);
            float p2 = PS(ty*4+2, k), p3 = PS(ty*4+3, k);
            float4 v4 = *(float4*)&VS(k, tx * 4);
            acc[0][0]+=p0*v4.x; acc[0][1]+=p0*v4.y; acc[0][2]+=p0*v4.z; acc[0][3]+=p0*v4.w;
            acc[1][0]+=p1*v4.x; acc[1][1]+=p1*v4.y; acc[1][2]+=p1*v4.z; acc[1][3]+=p1*v4.w;
            acc[2][0]+=p2*v4.x; acc[2][1]+=p2*v4.y; acc[2][2]+=p2*v4.z; acc[2][3]+=p2*v4.w;
            acc[3][0]+=p3*v4.x; acc[3][1]+=p3*v4.y; acc[3][2]+=p3*v4.z; acc[3][3]+=p3*v4.w;
        }
    }

    // normalize + store to [b, n, h*d]
    const int bb = bh >> 3;
    const int hh = bh & 7;
    #pragma unroll
    for (int i = 0; i < 4; i++) {
        int qi = qbase + ty * 4 + i;
        float inv = 1.0f / l_i[i];
        float* row = g_ao + ((size_t)(bb * NSEQ + qi)) * INNER + hh * DH + tx * 4;
        row[0] = acc[i][0] * inv; row[1] = acc[i][1] * inv;
        row[2] = acc[i][2] * inv; row[3] = acc[i][3] * inv;
    }
}

// ---------------------------------------------------------------------------
// Kernel 3: out = ao @ w_out + b_out  ([4096,512] x [512,512])
// ---------------------------------------------------------------------------
__global__ void out_gemm_kernel(const float* __restrict__ Bw,
                                const float* __restrict__ bias,
                                float* __restrict__ Cout)
{
    __shared__ float As[128][17];
    __shared__ float Bs[16][64];

    const int n0 = blockIdx.x * 64;
    const int m0 = blockIdx.y * 128;
    const int tid = threadIdx.x;
    const int tx = tid & 15, ty = tid >> 4;
    const float* A = g_ao;

    float c[8][4] = {};

    for (int k0 = 0; k0 < INNER; k0 += 16) {
        #pragma unroll
        for (int p = 0; p < 2; p++) {
            int id = tid + p * 256;
            int r  = id >> 2;
            int c4 = (id & 3) * 4;
            float4 a4 = *(const float4*)&A[(size_t)(m0 + r) * INNER + k0 + c4];
            As[r][c4+0] = a4.x; As[r][c4+1] = a4.y;
            As[r][c4+2] = a4.z; As[r][c4+3] = a4.w;
        }
        {
            int r  = tid >> 4;
            int c4 = (tid & 15) * 4;
            *(float4*)&Bs[r][c4] =
                *(const float4*)&Bw[(size_t)(k0 + r) * DIM + n0 + c4];
        }
        __syncthreads();

        #pragma unroll
        for (int kk = 0; kk < 16; kk++) {
            float4 b4 = *(float4*)&Bs[kk][tx * 4];
            #pragma unroll
            for (int i = 0; i < 8; i++) {
                float a = As[ty * 8 + i][kk];
                c[i][0] += a * b4.x; c[i][1] += a * b4.y;
                c[i][2] += a * b4.z; c[i][3] += a * b4.w;
            }
        }
        __syncthreads();
    }

    #pragma unroll
    for (int i = 0; i < 8; i++) {
        int m = m0 + ty * 8 + i;
        float* row = Cout + (size_t)m * DIM + n0 + tx * 4;
        const float* bptr = bias + n0 + tx * 4;
        row[0] = c[i][0] + bptr[0];
        row[1] = c[i][1] + bptr[1];
        row[2] = c[i][2] + bptr[2];
        row[3] = c[i][3] + bptr[3];
    }
}

// ---------------------------------------------------------------------------
extern "C" void kernel_launch(void* const* d_in, const int* in_sizes, int n_in,
                              void* d_out, int out_size)
{
    (void)in_sizes; (void)n_in; (void)out_size;
    const float* x      = (const float*)d_in[0];
    const float* w_qkv  = (const float*)d_in[1];
    const float* w_out  = (const float*)d_in[2];
    const float* b_out  = (const float*)d_in[3];
    float* out = (float*)d_out;

    const int attn_smem = (64*66 + 64*65 + 64*64 + 64*66) * 4;  // 66816 B
    cudaFuncSetAttribute(attn_kernel,
                         cudaFuncAttributeMaxDynamicSharedMemorySize, attn_smem);

    qkv_gemm_kernel<<<dim3(QKV_N / 64, M_TOT / 128), 256>>>(x, w_qkv);
    attn_kernel<<<dim3(NSEQ / 64, BATCH * H), 256, attn_smem>>>();
    out_gemm_kernel<<<dim3(DIM / 64, M_TOT / 128), 256>>>(w_out, b_out, out);
}